// round 6
// baseline (speedup 1.0000x reference)
#include <cuda_runtime.h>
#include <cstdint>

// Model_NPZD_68401649156380 — R6: per-WARP autonomous cp.async pipelines.
// Warp = 32 consecutive ODEs (t = W*32+lane; b = t/52, w = t%52).
// Forcing gathered in 7 chunks of 8 steps through a private 3-slot ring:
// while computing chunk c, chunks c+1 and c+2 are in flight. No __syncthreads
// anywhere in the hot path -> warps free-run -> continuous DRAM demand.
//
// idx(w,s) = 168w + 3s (exact). Chunk c, step i: col = 168w + 24c + 3i.
// Snapshots written straight to gmem (lane-private 128B line) each chunk.

#define NB      2048
#define NWK     52
#define NHRS    8760
#define DT      0.125f
#define NT      256
#define WARPS   (NT / 32)                 // 8
#define NCH     7
#define NSLOT   3
#define IPAD    9                         // float2 per ode per chunk (8+1)
#define SLOTF2  (32 * IPAD)               // 288 float2 per slot
#define WSLABF2 (NSLOT * SLOTF2)          // 864 float2 per warp
#define SMEM_BYTES (WARPS * WSLABF2 * (int)sizeof(float2))   // 55296
#define NWARPS_TOTAL ((NB * NWK) / 32)    // 3328
#define GRID    (NWARPS_TOTAL / WARPS)    // 416

__device__ __forceinline__ void issue_chunk(
    const float* __restrict__ gf, const float* __restrict__ gm,
    const int* goff,                // goff[r]: row base for ode_local r*4+(lane>>3)
    int c, float2* slot, int lane)
{
    uint32_t base = (uint32_t)__cvta_generic_to_shared(slot);
    const int i   = lane & 7;            // step within chunk handled by this lane
    const int col = 24 * c + 3 * i;
    #pragma unroll
    for (int r = 0; r < 8; ++r) {
        int ol = r * 4 + (lane >> 3);    // ode_local 0..31
        const float* fp = gf + goff[r] + col;
        const float* mp = gm + goff[r] + col;
        uint32_t dst = base + (uint32_t)((ol * IPAD + i) * 8);
        asm volatile("cp.async.ca.shared.global [%0], [%1], 4;\n"
                     :: "r"(dst), "l"(fp) : "memory");
        asm volatile("cp.async.ca.shared.global [%0], [%1], 4;\n"
                     :: "r"(dst + 4), "l"(mp) : "memory");
    }
    asm volatile("cp.async.commit_group;\n" ::: "memory");
}

__global__ __launch_bounds__(NT, 4) void npzd_kernel(
    const float* __restrict__ X_in,     // (B, 52, 5, 1)
    const float* __restrict__ gf,       // (B, 8760)
    const float* __restrict__ gm,       // (B, 8760)
    const float* __restrict__ pv,       // (B, 10)
    float* __restrict__ out)            // (B, 52, 4, 8)
{
    extern __shared__ float2 ring[];    // [WARPS][NSLOT][32][IPAD]
    const int lane = threadIdx.x & 31;
    const int wid  = threadIdx.x >> 5;
    const int W    = blockIdx.x * WARPS + wid;   // global warp id
    const int t    = W * 32 + lane;              // this lane's ODE
    const int b    = t / NWK;
    const int w    = t - b * NWK;

    float2* slab = ring + wid * WSLABF2;

    // Row bases for the 8 ode_locals this lane gathers for (fixed across chunks)
    int goff[8];
    #pragma unroll
    for (int r = 0; r < 8; ++r) {
        int t2 = W * 32 + r * 4 + (lane >> 3);
        int b2 = t2 / NWK;
        int w2 = t2 - b2 * NWK;
        goff[r] = b2 * NHRS + 168 * w2;
    }

    // Prime the pipeline: chunks 0 and 1 in flight.
    issue_chunk(gf, gm, goff, 0, slab + 0 * SLOTF2, lane);
    issue_chunk(gf, gm, goff, 1, slab + 1 * SLOTF2, lane);

    // Params + initial state (overlaps the first gathers).
    const float* p = pv + b * 10;
    const float chiC   = p[0];
    const float rho2   = p[1] * 2.0f;
    const float gam01  = p[2] * 0.1f;
    const float lam005 = p[3] * 0.05f;
    const float eps01  = p[4] * 0.1f;
    const float alp03  = p[5] * 0.3f;
    const float bet06  = p[6] * 0.6f;
    const float eta015 = p[7] * 0.15f;
    const float phi04  = p[8] * 0.4f;
    const float zet01  = p[9] * 0.1f;
    const float rem    = 1.0f - alp03 - bet06;

    const float* xi = X_in + (size_t)t * 5;
    float N = xi[1], P = xi[2], Z = xi[3], D = xi[4];

    // Initial snapshot (k = 0): lane-private 128B output line.
    float* op = out + (size_t)t * 32;
    op[0] = N; op[8] = P; op[16] = Z; op[24] = D;

    #pragma unroll 1
    for (int c = 0; c < NCH; ++c) {
        // chunk c landed (<=1 younger group pending)
        asm volatile("cp.async.wait_group 1;\n" ::: "memory");
        __syncwarp();

        // keep 2 chunks in flight: slot (c+2)%3 was consumed in iteration c-1
        if (c + 2 < NCH)
            issue_chunk(gf, gm, goff, c + 2,
                        slab + ((c + 2) % NSLOT) * SLOTF2, lane);

        const float2* sp = slab + (c % NSLOT) * SLOTF2 + lane * IPAD;
        #pragma unroll
        for (int i = 0; i < 8; ++i) {
            float2 fm = sp[i];
            float ft = fm.x, mt = fm.y;

            float Pc = fmaxf(0.01f, P);
            float Zc = fmaxf(0.01f, Z);
            float gN = N / (chiC + N);
            float zg = rho2 * (1.0f - __expf(-lam005 * Pc)) * Zc;
            float up = gN * ft * Pc;                    // Vm = 1

            float Nn = N + DT * (-up + alp03 * zg + eps01 * P + gam01 * Z
                                 + phi04 * D + mt * (8.0f - N));   // Q0 = 8
            float Pn = P + DT * (up - zg - eps01 * P - eta015 * P - mt * P);
            float Zn = Z + DT * (bet06 * zg - gam01 * Z - mt * Z);
            float Dn = D + DT * (eta015 * P + rem * zg - phi04 * D
                                 - zet01 * D - mt * D);
            N = Nn; P = Pn; Z = Zn; D = Dn;
        }
        __syncwarp();   // all lanes done reading slot c%3 before it is refilled

        // snapshot k = c+1 straight to gmem (L2 coalesces the 128B line)
        op[c + 1]      = N;
        op[8 + c + 1]  = P;
        op[16 + c + 1] = Z;
        op[24 + c + 1] = D;
    }
}

extern "C" void kernel_launch(void* const* d_in, const int* in_sizes, int n_in,
                              void* d_out, int out_size)
{
    (void)in_sizes; (void)n_in; (void)out_size;
    const float* X_in = (const float*)d_in[0];
    const float* gf   = (const float*)d_in[1];
    const float* gm   = (const float*)d_in[2];
    const float* pvv  = (const float*)d_in[3];
    float* out        = (float*)d_out;

    cudaFuncSetAttribute(npzd_kernel,
                         cudaFuncAttributeMaxDynamicSharedMemorySize,
                         SMEM_BYTES);
    npzd_kernel<<<GRID, NT, SMEM_BYTES>>>(X_in, gf, gm, pvv, out);
}